// round 13
// baseline (speedup 1.0000x reference)
#include <cuda_runtime.h>
#include <cuda_fp16.h>
#include <cstdint>

// x: (8,512,32,32) fp32 == xr[8192][512]; proj_w (512,512); proj_b (512)
// score_w (512); score_b (1); ln_w (25); ln_b (25); out (8,512,28,28) fp32

#define M_ROWS 8192
#define KDIM   512
#define ODIM   512
#define HH     28

// ---------------- scratch ----------------
__device__ __half g_projh[M_ROWS * ODIM];   // 8 MB  (fp16 proj, window's only input)
__device__ float g_score[M_ROWS];
__device__ float g_wall[8 * 784 * 25];      // softmax weights, 627 KB
__device__ __half g_A[M_ROWS * KDIM];       // 8 MB   (fp16(x))
__device__ __half g_W[ODIM * KDIM];         // 0.5 MB (fp16(w))

// ---------------- helpers ----------------
__device__ __forceinline__ uint32_t smem_u32(const void* p) {
    uint32_t a;
    asm("{ .reg .u64 t; cvta.to.shared.u64 t, %1; cvt.u32.u64 %0, t; }" : "=r"(a) : "l"(p));
    return a;
}
__device__ __forceinline__ void cp_async16(uint32_t sa, const void* ga) {
    asm volatile("cp.async.cg.shared.global [%0], [%1], 16;" :: "r"(sa), "l"(ga) : "memory");
}
__device__ __forceinline__ void cp_commit() {
    asm volatile("cp.async.commit_group;" ::: "memory");
}
__device__ __forceinline__ void cp_wait1() {
    asm volatile("cp.async.wait_group 1;" ::: "memory");
}
__device__ __forceinline__ void ldsm4(uint32_t* r, uint32_t a) {
    asm volatile("ldmatrix.sync.aligned.m8n8.x4.shared.b16 {%0,%1,%2,%3}, [%4];"
                 : "=r"(r[0]), "=r"(r[1]), "=r"(r[2]), "=r"(r[3]) : "r"(a));
}
__device__ __forceinline__ void mma_f16(float* c, const uint32_t* a, const uint32_t* b) {
    asm volatile(
        "mma.sync.aligned.m16n8k16.row.col.f32.f16.f16.f32 "
        "{%0,%1,%2,%3}, {%4,%5,%6,%7}, {%8,%9}, {%0,%1,%2,%3};"
        : "+f"(c[0]), "+f"(c[1]), "+f"(c[2]), "+f"(c[3])
        : "r"(a[0]), "r"(a[1]), "r"(a[2]), "r"(a[3]), "r"(b[0]), "r"(b[1]));
}

// ---------------- convert + score (2 rows/warp, MLP 8) ----------------
__global__ __launch_bounds__(256) void convert_kernel(const float* __restrict__ x,
                                                      const float* __restrict__ pw,
                                                      const float* __restrict__ sw,
                                                      const float* __restrict__ sb) {
    const int warp = blockIdx.x * 8 + (threadIdx.x >> 5);
    const int lane = threadIdx.x & 31;
    const int row0 = warp * 2;
    const bool isX = row0 < M_ROWS;
    const float* base = isX ? x + (size_t)row0 * KDIM
                            : pw + (size_t)(row0 - M_ROWS) * KDIM;
    const float4* s0 = (const float4*)base;
    const float4* s1 = (const float4*)(base + KDIM);

    float4 a0 = s0[2 * lane],      a1 = s0[2 * lane + 1];
    float4 a2 = s0[2 * lane + 64], a3 = s0[2 * lane + 65];
    float4 b0 = s1[2 * lane],      b1 = s1[2 * lane + 1];
    float4 b2 = s1[2 * lane + 64], b3 = s1[2 * lane + 65];

    __half2 ha0 = __floats2half2_rn(a0.x, a0.y), ha1 = __floats2half2_rn(a0.z, a0.w);
    __half2 ha2 = __floats2half2_rn(a1.x, a1.y), ha3 = __floats2half2_rn(a1.z, a1.w);
    __half2 ha4 = __floats2half2_rn(a2.x, a2.y), ha5 = __floats2half2_rn(a2.z, a2.w);
    __half2 ha6 = __floats2half2_rn(a3.x, a3.y), ha7 = __floats2half2_rn(a3.z, a3.w);
    __half2 hb0 = __floats2half2_rn(b0.x, b0.y), hb1 = __floats2half2_rn(b0.z, b0.w);
    __half2 hb2 = __floats2half2_rn(b1.x, b1.y), hb3 = __floats2half2_rn(b1.z, b1.w);
    __half2 hb4 = __floats2half2_rn(b2.x, b2.y), hb5 = __floats2half2_rn(b2.z, b2.w);
    __half2 hb6 = __floats2half2_rn(b3.x, b3.y), hb7 = __floats2half2_rn(b3.z, b3.w);
    uint4 ua, ub, uc, ud;
    ua.x = *(uint32_t*)&ha0; ua.y = *(uint32_t*)&ha1; ua.z = *(uint32_t*)&ha2; ua.w = *(uint32_t*)&ha3;
    ub.x = *(uint32_t*)&ha4; ub.y = *(uint32_t*)&ha5; ub.z = *(uint32_t*)&ha6; ub.w = *(uint32_t*)&ha7;
    uc.x = *(uint32_t*)&hb0; uc.y = *(uint32_t*)&hb1; uc.z = *(uint32_t*)&hb2; uc.w = *(uint32_t*)&hb3;
    ud.x = *(uint32_t*)&hb4; ud.y = *(uint32_t*)&hb5; ud.z = *(uint32_t*)&hb6; ud.w = *(uint32_t*)&hb7;

    __half* dbase = isX ? g_A + (size_t)row0 * KDIM
                        : g_W + (size_t)(row0 - M_ROWS) * KDIM;
    uint4* d0 = (uint4*)dbase;
    uint4* d1 = (uint4*)(dbase + KDIM);
    d0[lane] = ua; d0[lane + 32] = ub;
    d1[lane] = uc; d1[lane + 32] = ud;

    if (isX) {
        const float4* w4 = (const float4*)sw;
        float4 w0 = w4[2 * lane],      w1 = w4[2 * lane + 1];
        float4 w2 = w4[2 * lane + 64], w3 = w4[2 * lane + 65];
        float acc0 = a0.x * w0.x + a0.y * w0.y + a0.z * w0.z + a0.w * w0.w
                   + a1.x * w1.x + a1.y * w1.y + a1.z * w1.z + a1.w * w1.w
                   + a2.x * w2.x + a2.y * w2.y + a2.z * w2.z + a2.w * w2.w
                   + a3.x * w3.x + a3.y * w3.y + a3.z * w3.z + a3.w * w3.w;
        float acc1 = b0.x * w0.x + b0.y * w0.y + b0.z * w0.z + b0.w * w0.w
                   + b1.x * w1.x + b1.y * w1.y + b1.z * w1.z + b1.w * w1.w
                   + b2.x * w2.x + b2.y * w2.y + b2.z * w2.z + b2.w * w2.w
                   + b3.x * w3.x + b3.y * w3.y + b3.z * w3.z + b3.w * w3.w;
#pragma unroll
        for (int off = 16; off; off >>= 1) {
            acc0 += __shfl_xor_sync(0xffffffffu, acc0, off);
            acc1 += __shfl_xor_sync(0xffffffffu, acc1, off);
        }
        if (lane == 0) {
            float sbv = sb[0];
            g_score[row0] = acc0 + sbv;
            g_score[row0 + 1] = acc1 + sbv;
        }
    }
}

// ---------------- HMMA GEMM + piggybacked weight blocks ----------------
#define RGN     8192
#define STAGEB  (2 * RGN)
#define NIT     16

__device__ __forceinline__ uint32_t swz64(int r, int q) {
    return (uint32_t)(r * 64 + ((q ^ ((r >> 1) & 3)) << 4));
}

__global__ __launch_bounds__(256, 2) void gemm_mma(const float* __restrict__ bias,
                                                   const float* __restrict__ ln_w,
                                                   const float* __restrict__ ln_b) {
    __shared__ __align__(16) char smem[2 * STAGEB];   // 32KB

    // ---- weights blocks (y = 64, 65): LN + softmax for all windows of one n ----
    if (blockIdx.y >= 64) {
        const int n = ((int)blockIdx.y - 64) * 4 + (int)blockIdx.x;
        for (int widx = threadIdx.x; widx < 784; widx += 256) {
            const int hh = widx / 28;
            const int ww = widx - hh * 28;
            float v[25];
            float mu = 0.f;
#pragma unroll
            for (int ki = 0; ki < 5; ki++)
#pragma unroll
                for (int kj = 0; kj < 5; kj++) {
                    float tv = g_score[(size_t)n * 1024 + (hh + ki) * 32 + ww + kj];
                    v[ki * 5 + kj] = tv;
                    mu += tv;
                }
            mu *= (1.f / 25.f);
            float var = 0.f;
#pragma unroll
            for (int k = 0; k < 25; k++) {
                float d = v[k] - mu;
                var += d * d;
            }
            var *= (1.f / 25.f);
            float inv = rsqrtf(var + 1e-5f);
            float mx = -1e30f;
#pragma unroll
            for (int k = 0; k < 25; k++) {
                v[k] = (v[k] - mu) * inv * ln_w[k] + ln_b[k];
                mx = fmaxf(mx, v[k]);
            }
            float s = 0.f;
#pragma unroll
            for (int k = 0; k < 25; k++) {
                v[k] = __expf(v[k] - mx);
                s += v[k];
            }
            float r = 1.f / s;
            float* dst = g_wall + (size_t)n * 19600 + widx * 25;
#pragma unroll
            for (int k = 0; k < 25; k++) dst[k] = v[k] * r;
        }
        return;
    }

    // ---- GEMM tile blocks ----
    const int tid = threadIdx.x;
    const int lane = tid & 31;
    const int wid = tid >> 5;
    const int warpM = wid >> 1;
    const int warpN = wid & 1;
    const int bm = blockIdx.y * 128;
    const int bn = blockIdx.x * 128;
    const uint32_t sbase = smem_u32(smem);

    uint32_t ldst[4];
    const __half* lsrc[4];
#pragma unroll
    for (int i = 0; i < 4; i++) {
        int c = tid + 256 * i;
        int region = c >> 9;
        int r = (c & 511) >> 2;
        int q = c & 3;
        ldst[i] = sbase + region * RGN + swz64(r, q);
        const __half* base = (region == 0) ? g_A + (size_t)(bm + r) * KDIM
                                           : g_W + (size_t)(bn + r) * KDIM;
        lsrc[i] = base + q * 8;
    }

    const int t = lane >> 3;
    const int arow0 = warpM * 32 + (t & 1) * 8 + (lane & 7);
    const int brow = warpN * 64 + (t >> 1) * 8 + (lane & 7);
    const int aq = t >> 1;
    const int bq = t & 1;

    float acc[2][8][4];
#pragma unroll
    for (int i = 0; i < 2; i++)
#pragma unroll
        for (int j = 0; j < 8; j++)
#pragma unroll
            for (int q = 0; q < 4; q++) acc[i][j][q] = 0.f;

#pragma unroll
    for (int s = 0; s < 2; s++) {
#pragma unroll
        for (int i = 0; i < 4; i++) cp_async16(ldst[i] + s * STAGEB, lsrc[i] + s * 32);
        cp_commit();
    }

    for (int it = 0; it < NIT; it++) {
        cp_wait1();
        __syncthreads();
        const uint32_t stb = sbase + (it & 1) * STAGEB;

#pragma unroll
        for (int kk = 0; kk < 2; kk++) {
            uint32_t ah[2][4], bb[2][2][4];
            ldsm4(ah[0], stb + swz64(arow0, kk * 2 + aq));
            ldsm4(ah[1], stb + swz64(arow0 + 16, kk * 2 + aq));
            ldsm4(bb[0][0], stb + RGN + swz64(brow, kk * 2 + bq));
            ldsm4(bb[0][1], stb + RGN + swz64(brow + 16, kk * 2 + bq));
            ldsm4(bb[1][0], stb + RGN + swz64(brow + 32, kk * 2 + bq));
            ldsm4(bb[1][1], stb + RGN + swz64(brow + 48, kk * 2 + bq));
            if (kk == 1) {
                __syncthreads();
                if (it + 2 < NIT) {
#pragma unroll
                    for (int i = 0; i < 4; i++)
                        cp_async16(ldst[i] + (it & 1) * STAGEB, lsrc[i] + (it + 2) * 32);
                }
                cp_commit();
            }
#pragma unroll
            for (int h = 0; h < 2; h++)
#pragma unroll
                for (int mt = 0; mt < 2; mt++)
#pragma unroll
                    for (int ntl = 0; ntl < 4; ntl++)
                        mma_f16(acc[mt][h * 4 + ntl], ah[mt], &bb[h][ntl >> 1][(ntl & 1) * 2]);
        }
    }

    // epilogue: acc + bias -> fp16 g_projh
#pragma unroll
    for (int nt = 0; nt < 8; nt++) {
        const int c = bn + warpN * 64 + nt * 8 + (lane & 3) * 2;
        float2 bbias = *(const float2*)&bias[c];
#pragma unroll
        for (int mt = 0; mt < 2; mt++) {
            const int r = bm + warpM * 32 + mt * 16 + (lane >> 2);
            __half2 h0 = __floats2half2_rn(acc[mt][nt][0] + bbias.x, acc[mt][nt][1] + bbias.y);
            __half2 h1 = __floats2half2_rn(acc[mt][nt][2] + bbias.x, acc[mt][nt][3] + bbias.y);
            *(uint32_t*)&g_projh[(size_t)r * ODIM + c] = *(uint32_t*)&h0;
            *(uint32_t*)&g_projh[(size_t)(r + 8) * ODIM + c] = *(uint32_t*)&h1;
        }
    }
}

// ---------------- window attention (fp16 taps, 8-ch threads, 2 hh rows/block) ----------------
// grid (14, 8, 2): block = (hh pair, n, channel-half). 256 threads = 32 ww-lanes x 8 cq-warps.
// SMEM tile rows are 144B (72 halves, 64 used) -> 36-word stride, conflict-free LDS.128.
#define WROW 144

__global__ __launch_bounds__(256) void window_kernel(float* __restrict__ out) {
    __shared__ __align__(16) char psb[6 * 32 * WROW];   // 27648 B
    __shared__ float s_w[2][28][25];                    // 5600 B

    const int hh0 = blockIdx.x * 2;
    const int n = blockIdx.y;
    const int cbase = blockIdx.z * 256;
    const int tid = threadIdx.x;

    // weights for rows hh0, hh0+1: 1400 floats = 350 float4
    for (int i = tid; i < 350; i += 256) {
        float4 v = ((const float4*)(g_wall + (size_t)n * 19600 + hh0 * 700))[i];
        ((float4*)&s_w[0][0][0])[i] = v;
    }

    const int ww = tid & 31;
    const int cq = tid >> 5;          // 0..7 -> 8 channels each
    const bool act = (ww < HH);
    const int wsrc = act ? ww : 0;

#pragma unroll
    for (int cc = 0; cc < 4; cc++) {
        const int c0 = cbase + cc * 64;
        __syncthreads();
        // stage 6 rows x 32 w x 64 halves = 1536 uint4 (16B = 8 halves each)
        for (int i = tid; i < 1536; i += 256) {
            int pos = i >> 3;         // ki*32 + w
            int q = i & 7;
            int ki = pos >> 5, w = pos & 31;
            *(uint4*)(psb + pos * WROW + q * 16) =
                *(const uint4*)&g_projh[(size_t)((n * 32 + hh0 + ki) * 32 + w) * ODIM + c0 + q * 8];
        }
        __syncthreads();
#pragma unroll
        for (int hi = 0; hi < 2; hi++) {
            float wt[25];
#pragma unroll
            for (int k = 0; k < 25; k++) wt[k] = s_w[hi][wsrc][k];
            if (act) {
                float4 acc0 = {0.f, 0.f, 0.f, 0.f};
                float4 acc1 = {0.f, 0.f, 0.f, 0.f};
#pragma unroll
                for (int ki = 0; ki < 5; ki++)
#pragma unroll
                    for (int kj = 0; kj < 5; kj++) {
                        const float wv = wt[ki * 5 + kj];
                        uint4 v = *(const uint4*)(psb + ((hi + ki) * 32 + ww + kj) * WROW + cq * 16);
                        float2 f0 = __half22float2(*(__half2*)&v.x);
                        float2 f1 = __half22float2(*(__half2*)&v.y);
                        float2 f2 = __half22float2(*(__half2*)&v.z);
                        float2 f3 = __half22float2(*(__half2*)&v.w);
                        acc0.x = fmaf(wv, f0.x, acc0.x);
                        acc0.y = fmaf(wv, f0.y, acc0.y);
                        acc0.z = fmaf(wv, f1.x, acc0.z);
                        acc0.w = fmaf(wv, f1.y, acc0.w);
                        acc1.x = fmaf(wv, f2.x, acc1.x);
                        acc1.y = fmaf(wv, f2.y, acc1.y);
                        acc1.z = fmaf(wv, f3.x, acc1.z);
                        acc1.w = fmaf(wv, f3.y, acc1.w);
                    }
                const int c = c0 + cq * 8;
                size_t ob = ((size_t)(n * 512 + c) * HH + hh0 + hi) * HH + ww;
                out[ob] = acc0.x;
                out[ob + 784] = acc0.y;
                out[ob + 1568] = acc0.z;
                out[ob + 2352] = acc0.w;
                out[ob + 3136] = acc1.x;
                out[ob + 3920] = acc1.y;
                out[ob + 4704] = acc1.z;
                out[ob + 5488] = acc1.w;
            }
        }
    }
}

extern "C" void kernel_launch(void* const* d_in, const int* in_sizes, int n_in,
                              void* d_out, int out_size) {
    const float* x       = (const float*)d_in[0];
    const float* proj_w  = (const float*)d_in[1];
    const float* proj_b  = (const float*)d_in[2];
    const float* score_w = (const float*)d_in[3];
    const float* score_b = (const float*)d_in[4];
    const float* ln_w    = (const float*)d_in[5];
    const float* ln_b    = (const float*)d_in[6];
    float* out = (float*)d_out;

    convert_kernel<<<544, 256>>>(x, proj_w, score_w, score_b);
    gemm_mma<<<dim3(4, 66), 256>>>(proj_b, ln_w, ln_b);
    window_kernel<<<dim3(14, 8, 2), 256>>>(out);
}

// round 14
// speedup vs baseline: 1.1797x; 1.1797x over previous
#include <cuda_runtime.h>
#include <cuda_fp16.h>
#include <cstdint>

// x: (8,512,32,32) fp32 == xr[8192][512]; proj_w (512,512); proj_b (512)
// score_w (512); score_b (1); ln_w (25); ln_b (25); out (8,512,28,28) fp32

#define M_ROWS 8192
#define KDIM   512
#define ODIM   512
#define HH     28

// ---------------- scratch ----------------
__device__ float g_proj[M_ROWS * ODIM];     // 16 MB
__device__ float g_score[M_ROWS];
__device__ float g_wall[8 * 784 * 25];      // softmax weights, 627 KB
__device__ __half g_A[M_ROWS * KDIM];       // 8 MB   (fp16(x))
__device__ __half g_W[ODIM * KDIM];         // 0.5 MB (fp16(w))

// ---------------- helpers ----------------
__device__ __forceinline__ uint32_t smem_u32(const void* p) {
    uint32_t a;
    asm("{ .reg .u64 t; cvta.to.shared.u64 t, %1; cvt.u32.u64 %0, t; }" : "=r"(a) : "l"(p));
    return a;
}
__device__ __forceinline__ void cp_async16(uint32_t sa, const void* ga) {
    asm volatile("cp.async.cg.shared.global [%0], [%1], 16;" :: "r"(sa), "l"(ga) : "memory");
}
__device__ __forceinline__ void cp_commit() {
    asm volatile("cp.async.commit_group;" ::: "memory");
}
__device__ __forceinline__ void cp_wait1() {
    asm volatile("cp.async.wait_group 1;" ::: "memory");
}
__device__ __forceinline__ void ldsm4(uint32_t* r, uint32_t a) {
    asm volatile("ldmatrix.sync.aligned.m8n8.x4.shared.b16 {%0,%1,%2,%3}, [%4];"
                 : "=r"(r[0]), "=r"(r[1]), "=r"(r[2]), "=r"(r[3]) : "r"(a));
}
__device__ __forceinline__ void mma_f16(float* c, const uint32_t* a, const uint32_t* b) {
    asm volatile(
        "mma.sync.aligned.m16n8k16.row.col.f32.f16.f16.f32 "
        "{%0,%1,%2,%3}, {%4,%5,%6,%7}, {%8,%9}, {%0,%1,%2,%3};"
        : "+f"(c[0]), "+f"(c[1]), "+f"(c[2]), "+f"(c[3])
        : "r"(a[0]), "r"(a[1]), "r"(a[2]), "r"(a[3]), "r"(b[0]), "r"(b[1]));
}

// ---------------- convert + score (4 rows/warp, MLP 16) ----------------
__global__ __launch_bounds__(256) void convert_kernel(const float* __restrict__ x,
                                                      const float* __restrict__ pw,
                                                      const float* __restrict__ sw,
                                                      const float* __restrict__ sb) {
    const int warp = blockIdx.x * 8 + (threadIdx.x >> 5);
    const int lane = threadIdx.x & 31;
    const int row0 = warp * 4;                 // 4 consecutive rows; 8192 % 4 == 0
    const bool isX = row0 < M_ROWS;
    const float* base = isX ? x + (size_t)row0 * KDIM
                            : pw + (size_t)(row0 - M_ROWS) * KDIM;

    // 16 independent loads up front (MLP 16)
    float4 v[4][4];
#pragma unroll
    for (int r = 0; r < 4; r++) {
        const float4* s = (const float4*)(base + (size_t)r * KDIM);
        v[r][0] = s[2 * lane];
        v[r][1] = s[2 * lane + 1];
        v[r][2] = s[2 * lane + 64];
        v[r][3] = s[2 * lane + 65];
    }

    // convert all rows to fp16
    uint4 u[4][2];
#pragma unroll
    for (int r = 0; r < 4; r++) {
        __half2 h0 = __floats2half2_rn(v[r][0].x, v[r][0].y);
        __half2 h1 = __floats2half2_rn(v[r][0].z, v[r][0].w);
        __half2 h2 = __floats2half2_rn(v[r][1].x, v[r][1].y);
        __half2 h3 = __floats2half2_rn(v[r][1].z, v[r][1].w);
        __half2 h4 = __floats2half2_rn(v[r][2].x, v[r][2].y);
        __half2 h5 = __floats2half2_rn(v[r][2].z, v[r][2].w);
        __half2 h6 = __floats2half2_rn(v[r][3].x, v[r][3].y);
        __half2 h7 = __floats2half2_rn(v[r][3].z, v[r][3].w);
        u[r][0].x = *(uint32_t*)&h0; u[r][0].y = *(uint32_t*)&h1;
        u[r][0].z = *(uint32_t*)&h2; u[r][0].w = *(uint32_t*)&h3;
        u[r][1].x = *(uint32_t*)&h4; u[r][1].y = *(uint32_t*)&h5;
        u[r][1].z = *(uint32_t*)&h6; u[r][1].w = *(uint32_t*)&h7;
    }

    __half* dbase = isX ? g_A + (size_t)row0 * KDIM
                        : g_W + (size_t)(row0 - M_ROWS) * KDIM;
#pragma unroll
    for (int r = 0; r < 4; r++) {
        uint4* d = (uint4*)(dbase + (size_t)r * KDIM);
        d[lane] = u[r][0];
        d[lane + 32] = u[r][1];
    }

    if (isX) {
        // score_w loaded once, reused for all 4 rows
        const float4* w4 = (const float4*)sw;
        float4 w0 = w4[2 * lane],      w1 = w4[2 * lane + 1];
        float4 w2 = w4[2 * lane + 64], w3 = w4[2 * lane + 65];
        float acc[4];
#pragma unroll
        for (int r = 0; r < 4; r++) {
            acc[r] = v[r][0].x * w0.x + v[r][0].y * w0.y + v[r][0].z * w0.z + v[r][0].w * w0.w
                   + v[r][1].x * w1.x + v[r][1].y * w1.y + v[r][1].z * w1.z + v[r][1].w * w1.w
                   + v[r][2].x * w2.x + v[r][2].y * w2.y + v[r][2].z * w2.z + v[r][2].w * w2.w
                   + v[r][3].x * w3.x + v[r][3].y * w3.y + v[r][3].z * w3.z + v[r][3].w * w3.w;
        }
#pragma unroll
        for (int off = 16; off; off >>= 1) {
#pragma unroll
            for (int r = 0; r < 4; r++)
                acc[r] += __shfl_xor_sync(0xffffffffu, acc[r], off);
        }
        if (lane == 0) {
            float sbv = sb[0];
#pragma unroll
            for (int r = 0; r < 4; r++) g_score[row0 + r] = acc[r] + sbv;
        }
    }
}

// ---------------- HMMA GEMM + piggybacked weight blocks ----------------
#define RGN     8192
#define STAGEB  (2 * RGN)
#define NIT     16

__device__ __forceinline__ uint32_t swz64(int r, int q) {
    return (uint32_t)(r * 64 + ((q ^ ((r >> 1) & 3)) << 4));
}

__global__ __launch_bounds__(256, 2) void gemm_mma(const float* __restrict__ bias,
                                                   const float* __restrict__ ln_w,
                                                   const float* __restrict__ ln_b) {
    __shared__ __align__(16) char smem[2 * STAGEB];   // 32KB

    // ---- weights blocks (y = 64, 65): LN + softmax for all windows of one n ----
    if (blockIdx.y >= 64) {
        const int n = ((int)blockIdx.y - 64) * 4 + (int)blockIdx.x;
        for (int widx = threadIdx.x; widx < 784; widx += 256) {
            const int hh = widx / 28;
            const int ww = widx - hh * 28;
            float v[25];
            float mu = 0.f;
#pragma unroll
            for (int ki = 0; ki < 5; ki++)
#pragma unroll
                for (int kj = 0; kj < 5; kj++) {
                    float tv = g_score[(size_t)n * 1024 + (hh + ki) * 32 + ww + kj];
                    v[ki * 5 + kj] = tv;
                    mu += tv;
                }
            mu *= (1.f / 25.f);
            float var = 0.f;
#pragma unroll
            for (int k = 0; k < 25; k++) {
                float d = v[k] - mu;
                var += d * d;
            }
            var *= (1.f / 25.f);
            float inv = rsqrtf(var + 1e-5f);
            float mx = -1e30f;
#pragma unroll
            for (int k = 0; k < 25; k++) {
                v[k] = (v[k] - mu) * inv * ln_w[k] + ln_b[k];
                mx = fmaxf(mx, v[k]);
            }
            float s = 0.f;
#pragma unroll
            for (int k = 0; k < 25; k++) {
                v[k] = __expf(v[k] - mx);
                s += v[k];
            }
            float r = 1.f / s;
            float* dst = g_wall + (size_t)n * 19600 + widx * 25;
#pragma unroll
            for (int k = 0; k < 25; k++) dst[k] = v[k] * r;
        }
        return;
    }

    // ---- GEMM tile blocks ----
    const int tid = threadIdx.x;
    const int lane = tid & 31;
    const int wid = tid >> 5;
    const int warpM = wid >> 1;
    const int warpN = wid & 1;
    const int bm = blockIdx.y * 128;
    const int bn = blockIdx.x * 128;
    const uint32_t sbase = smem_u32(smem);

    uint32_t ldst[4];
    const __half* lsrc[4];
#pragma unroll
    for (int i = 0; i < 4; i++) {
        int c = tid + 256 * i;
        int region = c >> 9;
        int r = (c & 511) >> 2;
        int q = c & 3;
        ldst[i] = sbase + region * RGN + swz64(r, q);
        const __half* base = (region == 0) ? g_A + (size_t)(bm + r) * KDIM
                                           : g_W + (size_t)(bn + r) * KDIM;
        lsrc[i] = base + q * 8;
    }

    const int t = lane >> 3;
    const int arow0 = warpM * 32 + (t & 1) * 8 + (lane & 7);
    const int brow = warpN * 64 + (t >> 1) * 8 + (lane & 7);
    const int aq = t >> 1;
    const int bq = t & 1;

    float acc[2][8][4];
#pragma unroll
    for (int i = 0; i < 2; i++)
#pragma unroll
        for (int j = 0; j < 8; j++)
#pragma unroll
            for (int q = 0; q < 4; q++) acc[i][j][q] = 0.f;

#pragma unroll
    for (int s = 0; s < 2; s++) {
#pragma unroll
        for (int i = 0; i < 4; i++) cp_async16(ldst[i] + s * STAGEB, lsrc[i] + s * 32);
        cp_commit();
    }

    for (int it = 0; it < NIT; it++) {
        cp_wait1();
        __syncthreads();
        const uint32_t stb = sbase + (it & 1) * STAGEB;

#pragma unroll
        for (int kk = 0; kk < 2; kk++) {
            uint32_t ah[2][4], bb[2][2][4];
            ldsm4(ah[0], stb + swz64(arow0, kk * 2 + aq));
            ldsm4(ah[1], stb + swz64(arow0 + 16, kk * 2 + aq));
            ldsm4(bb[0][0], stb + RGN + swz64(brow, kk * 2 + bq));
            ldsm4(bb[0][1], stb + RGN + swz64(brow + 16, kk * 2 + bq));
            ldsm4(bb[1][0], stb + RGN + swz64(brow + 32, kk * 2 + bq));
            ldsm4(bb[1][1], stb + RGN + swz64(brow + 48, kk * 2 + bq));
            if (kk == 1) {
                __syncthreads();
                if (it + 2 < NIT) {
#pragma unroll
                    for (int i = 0; i < 4; i++)
                        cp_async16(ldst[i] + (it & 1) * STAGEB, lsrc[i] + (it + 2) * 32);
                }
                cp_commit();
            }
#pragma unroll
            for (int h = 0; h < 2; h++)
#pragma unroll
                for (int mt = 0; mt < 2; mt++)
#pragma unroll
                    for (int ntl = 0; ntl < 4; ntl++)
                        mma_f16(acc[mt][h * 4 + ntl], ah[mt], &bb[h][ntl >> 1][(ntl & 1) * 2]);
        }
    }

#pragma unroll
    for (int nt = 0; nt < 8; nt++) {
        const int c = bn + warpN * 64 + nt * 8 + (lane & 3) * 2;
        float2 bbias = *(const float2*)&bias[c];
#pragma unroll
        for (int mt = 0; mt < 2; mt++) {
            const int r = bm + warpM * 32 + mt * 16 + (lane >> 2);
            float2 o0 = {acc[mt][nt][0] + bbias.x, acc[mt][nt][1] + bbias.y};
            float2 o1 = {acc[mt][nt][2] + bbias.x, acc[mt][nt][3] + bbias.y};
            *(float2*)&g_proj[(size_t)r * ODIM + c] = o0;
            *(float2*)&g_proj[(size_t)(r + 8) * ODIM + c] = o1;
        }
    }
}

// ---------------- window attention (R10 inner sweep, 2 hh rows per block) ----------------
// grid (14, 8, 2): block = (hh pair, n, channel-half). 256 threads.
#define WIN_SMEM (6 * 32 * 68 * 4 + 2 * 28 * 25 * 4 + 256)   // 52224 + 5600 + pad

__global__ __launch_bounds__(256) void window_kernel(float* __restrict__ out) {
    extern __shared__ __align__(16) char wsm[];
    float (*ps)[32][68] = (float (*)[32][68])wsm;                  // [6][32][68]
    float (*s_w)[28][25] = (float (*)[28][25])(wsm + 6 * 32 * 68 * 4);  // [2][28][25]

    const int hh0 = blockIdx.x * 2;
    const int n = blockIdx.y;
    const int cbase = blockIdx.z * 256;
    const int tid = threadIdx.x;

    // weights for rows hh0, hh0+1: 1400 floats = 350 float4
    for (int i = tid; i < 350; i += 256) {
        float4 v = ((const float4*)(g_wall + (size_t)n * 19600 + hh0 * 700))[i];
        ((float4*)&s_w[0][0][0])[i] = v;
    }

    const int ww = tid & 31;
    const int cq = tid >> 5;
    const bool act = (ww < HH);
    const int wsrc = act ? ww : 0;

#pragma unroll
    for (int cc = 0; cc < 4; cc++) {
        const int c0 = cbase + cc * 64;
        __syncthreads();
        // stage 6 rows x 32 w x 64 ch = 3072 float4
        for (int i = tid; i < 3072; i += 256) {
            int pos = i >> 4;
            int q = i & 15;
            int ki = pos >> 5, w = pos & 31;
            *(float4*)&ps[ki][w][q << 2] =
                *(const float4*)&g_proj[(size_t)((n * 32 + hh0 + ki) * 32 + w) * ODIM + c0 + (q << 2)];
        }
        __syncthreads();
#pragma unroll
        for (int hi = 0; hi < 2; hi++) {
            float wt[25];
#pragma unroll
            for (int k = 0; k < 25; k++) wt[k] = s_w[hi][wsrc][k];
            if (act) {
#pragma unroll
                for (int rep = 0; rep < 2; rep++) {
                    int cq4 = cq + rep * 8;
                    float4 acc = {0.f, 0.f, 0.f, 0.f};
#pragma unroll
                    for (int ki = 0; ki < 5; ki++)
#pragma unroll
                        for (int kj = 0; kj < 5; kj++) {
                            float wv = wt[ki * 5 + kj];
                            float4 p = *(const float4*)&ps[hi + ki][ww + kj][cq4 << 2];
                            acc.x = fmaf(wv, p.x, acc.x);
                            acc.y = fmaf(wv, p.y, acc.y);
                            acc.z = fmaf(wv, p.z, acc.z);
                            acc.w = fmaf(wv, p.w, acc.w);
                        }
                    int c = c0 + (cq4 << 2);
                    size_t ob = ((size_t)(n * 512 + c) * HH + hh0 + hi) * HH + ww;
                    out[ob] = acc.x;
                    out[ob + 784] = acc.y;
                    out[ob + 1568] = acc.z;
                    out[ob + 2352] = acc.w;
                }
            }
        }
    }
}

extern "C" void kernel_launch(void* const* d_in, const int* in_sizes, int n_in,
                              void* d_out, int out_size) {
    const float* x       = (const float*)d_in[0];
    const float* proj_w  = (const float*)d_in[1];
    const float* proj_b  = (const float*)d_in[2];
    const float* score_w = (const float*)d_in[3];
    const float* score_b = (const float*)d_in[4];
    const float* ln_w    = (const float*)d_in[5];
    const float* ln_b    = (const float*)d_in[6];
    float* out = (float*)d_out;

    cudaFuncSetAttribute(window_kernel, cudaFuncAttributeMaxDynamicSharedMemorySize, WIN_SMEM);

    convert_kernel<<<272, 256>>>(x, proj_w, score_w, score_b);
    gemm_mma<<<dim3(4, 66), 256>>>(proj_b, ln_w, ln_b);
    window_kernel<<<dim3(14, 8, 2), 256, WIN_SMEM>>>(out);
}